// round 16
// baseline (speedup 1.0000x reference)
#include <cuda_runtime.h>
#include <cuda_bf16.h>
#include <math.h>
#include <stdint.h>

#define BATCH 4
#define DIMC  256
#define DI    256
#define NS    16
#define NPT   4096
#define NC    64
#define CL    64

// ---- mma.sync + cp.async helpers ----
__device__ __forceinline__ uint32_t smem_u32(const void* p) {
    uint32_t a; asm("{ .reg .u64 t; cvta.to.shared.u64 t, %1; cvt.u32.u64 %0, t; }" : "=r"(a) : "l"(p));
    return a;
}
__device__ __forceinline__ void mma_bf16(float* c, const uint32_t* a, const uint32_t* b) {
    asm volatile(
        "mma.sync.aligned.m16n8k16.row.col.f32.bf16.bf16.f32 "
        "{%0,%1,%2,%3}, {%4,%5,%6,%7}, {%8,%9}, {%0,%1,%2,%3};"
        : "+f"(c[0]), "+f"(c[1]), "+f"(c[2]), "+f"(c[3])
        : "r"(a[0]), "r"(a[1]), "r"(a[2]), "r"(a[3]), "r"(b[0]), "r"(b[1]));
}
__device__ __forceinline__ void ldsm4(uint32_t* r, uint32_t addr) {
    asm volatile("ldmatrix.sync.aligned.m8n8.x4.shared.b16 {%0,%1,%2,%3}, [%4];"
        : "=r"(r[0]), "=r"(r[1]), "=r"(r[2]), "=r"(r[3]) : "r"(addr));
}
__device__ __forceinline__ void ldsm2(uint32_t* r, uint32_t addr) {
    asm volatile("ldmatrix.sync.aligned.m8n8.x2.shared.b16 {%0,%1}, [%2];"
        : "=r"(r[0]), "=r"(r[1]) : "r"(addr));
}
__device__ __forceinline__ void cpa16(uint32_t s, const void* g) {
    asm volatile("cp.async.cg.shared.global [%0], [%1], 16;"
        :: "r"(s), "l"(__cvta_generic_to_global(g)));
}
#define CPA_COMMIT() asm volatile("cp.async.commit_group;" ::: "memory")

// ---------------- scratch (device globals) ----------------
static __device__ float g_x1T[BATCH*NPT*DI];        // in_proj x1 half, TRANSPOSED [b][n][d]
static __device__ float g_deltaT[BATCH*NPT*DI];
static __device__ float g_Bm[BATCH*NPT*NS];
static __device__ float g_Cm[BATCH*NPT*NS];
static __device__ float g_P[BATCH*NC*NS*DI];
static __device__ float g_H0[BATCH*NC*NS*DI];
static __device__ float g_A[DI*NS];
static __device__ float g_aL[DI*NS];
static __device__ __nv_bfloat16 g_whi[512*256];
static __device__ __nv_bfloat16 g_wlo[512*256];
static __device__ __nv_bfloat16 g_wohi[256*256];
static __device__ __nv_bfloat16 g_wolo[256*256];
static __device__ __nv_bfloat16 g_wbchi[32*256];
static __device__ __nv_bfloat16 g_wbclo[32*256];
static __device__ __nv_bfloat16 g_xthi[BATCH*NPT*DIMC];  // [b][n][c]
static __device__ __nv_bfloat16 g_xtlo[BATCH*NPT*DIMC];
static __device__ __nv_bfloat16 g_xshi[BATCH*NPT*DI];    // silu(conv) [b][n][d]
static __device__ __nv_bfloat16 g_xslo[BATCH*NPT*DI];
static __device__ __nv_bfloat16 g_yhi[BATCH*NPT*DI];     // [b][n][d]
static __device__ __nv_bfloat16 g_ylo[BATCH*NPT*DI];

// ---------------- K-prep ------------------------------------------------------
__global__ void k_prep(const float* __restrict__ A_log, const float* __restrict__ w_in,
                       const float* __restrict__ w_out, const float* __restrict__ Bw,
                       const float* __restrict__ Cw, const float* __restrict__ x) {
    int blk = blockIdx.x, tid = threadIdx.x;
    if (blk < 512) {
        int i = blk*256 + tid;
        float v = w_in[i];
        __nv_bfloat16 hi = __float2bfloat16(v);
        g_whi[i] = hi;
        g_wlo[i] = __float2bfloat16(v - __bfloat162float(hi));
    } else if (blk < 768) {
        int i = (blk-512)*256 + tid;
        float v = w_out[i];
        __nv_bfloat16 hi = __float2bfloat16(v);
        g_wohi[i] = hi;
        g_wolo[i] = __float2bfloat16(v - __bfloat162float(hi));
    } else if (blk < 784) {
        int i = (blk-768)*256 + tid;
        if (i < DI*NS) {
            float al = A_log[i];
            g_A[i]  = -expf(al);
            g_aL[i] =  expf((float)CL * al);   // CL even
        }
    } else if (blk < 816) {
        int i = (blk-784)*256 + tid;
        float v = (i < 4096) ? Bw[i] : Cw[i - 4096];
        __nv_bfloat16 hi = __float2bfloat16(v);
        g_wbchi[i] = hi;
        g_wbclo[i] = __float2bfloat16(v - __bfloat162float(hi));
    } else {
        __shared__ float s[64][33];
        int t = blk - 816;                 // 0..2047
        int b = t >> 9, rem = t & 511;
        int ct = rem >> 7, nt = rem & 127; // 4 c-tiles x 128 n-tiles
        int c0 = ct*64, n0 = nt*32;
        int tx = tid & 31, ty = tid >> 5;
        #pragma unroll
        for (int i = 0; i < 64; i += 8)
            s[ty+i][tx] = x[((size_t)b*DIMC + c0+ty+i)*NPT + n0 + tx];
        __syncthreads();
        #pragma unroll
        for (int j = 0; j < 4; j++) {
            int n = ty + j*8;
            int c = tx*2;
            float v0 = s[c][n], v1 = s[c+1][n];
            __nv_bfloat16 h0 = __float2bfloat16(v0), h1 = __float2bfloat16(v1);
            __nv_bfloat16 l0 = __float2bfloat16(v0 - __bfloat162float(h0));
            __nv_bfloat16 l1 = __float2bfloat16(v1 - __bfloat162float(h1));
            size_t idx = ((size_t)b*NPT + n0+n)*DIMC + c0 + c;
            __nv_bfloat162 hh; hh.x = h0; hh.y = h1;
            __nv_bfloat162 ll; ll.x = l0; ll.y = l1;
            *(__nv_bfloat162*)&g_xthi[idx] = hh;
            *(__nv_bfloat162*)&g_xtlo[idx] = ll;
        }
    }
}

// ---------------- K1: in_proj mma.sync, split x1/z halves, stream-parallel ---
// zflag=0: rows [0,256) -> g_x1T.  zflag=1: rows [256,512) -> sigmoid -> g_deltaT.
#define SAS 40
#define ARR_B (128*SAS*2)
#define STG_B (4*ARR_B)
#define MMA_DSM (2*STG_B)
__global__ void __launch_bounds__(256) k_mma_in(const float* __restrict__ bias, int zflag) {
    extern __shared__ char dsm[];
    uint32_t sb = smem_u32(dsm);
    int tid = threadIdx.x, lane = tid & 31, wid = tid >> 5;
    int wm = wid & 1, wn = wid >> 1;
    int nt = blockIdx.x, mt = blockIdx.y, b = blockIdx.z;
    int d0base = mt*128;
    int o0 = d0base + (zflag ? 256 : 0);
    int n0 = nt*128;

    float acc[4][4][4];
    #pragma unroll
    for (int i = 0; i < 4; i++)
        #pragma unroll
        for (int j = 0; j < 4; j++)
            #pragma unroll
            for (int q = 0; q < 4; q++) acc[i][j][q] = 0.f;

    auto issue = [&](int k, int stg) {
        uint32_t sbase = sb + (uint32_t)stg*STG_B;
        int k0 = k*32;
        #pragma unroll
        for (int i = 0; i < 2; i++) {
            int idx = tid + i*256;
            int row = idx >> 2, seg = idx & 3;
            uint32_t so = (uint32_t)((row*SAS + seg*8)*2);
            size_t ga = (size_t)(o0 + row)*256 + k0 + seg*8;
            size_t gb = ((size_t)b*NPT + n0 + row)*DIMC + k0 + seg*8;
            cpa16(sbase + so,             &g_whi[ga]);
            cpa16(sbase + ARR_B + so,     &g_wlo[ga]);
            cpa16(sbase + 2*ARR_B + so,   &g_xthi[gb]);
            cpa16(sbase + 3*ARR_B + so,   &g_xtlo[gb]);
        }
        CPA_COMMIT();
    };

    uint32_t aoff = (uint32_t)(((wm*64 + (lane&15))*SAS + (lane>>4)*8) * 2);
    uint32_t boff = (uint32_t)(((wn*32 + (lane&7))*SAS + ((lane>>3)&1)*8) * 2);

    issue(0, 0);
    issue(1, 1);

    #pragma unroll
    for (int k = 0; k < 8; k++) {
        if (k < 7) asm volatile("cp.async.wait_group 1;" ::: "memory");
        else       asm volatile("cp.async.wait_group 0;" ::: "memory");
        __syncthreads();
        int stg = k & 1;
        uint32_t aBase = sb + (uint32_t)stg*STG_B + aoff;
        uint32_t bBase = sb + (uint32_t)stg*STG_B + 2*ARR_B + boff;
        #pragma unroll
        for (int ks = 0; ks < 2; ks++) {
            uint32_t koff = ks*32;
            uint32_t ah[4][4], al[4][4], bh[4][2], bl[4][2];
            #pragma unroll
            for (int mi = 0; mi < 4; mi++) {
                ldsm4(ah[mi], aBase + mi*(16*SAS*2) + koff);
                ldsm4(al[mi], aBase + ARR_B + mi*(16*SAS*2) + koff);
            }
            #pragma unroll
            for (int ni = 0; ni < 4; ni++) {
                ldsm2(bh[ni], bBase + ni*(8*SAS*2) + koff);
                ldsm2(bl[ni], bBase + ARR_B + ni*(8*SAS*2) + koff);
            }
            #pragma unroll
            for (int mi = 0; mi < 4; mi++)
                #pragma unroll
                for (int ni = 0; ni < 4; ni++) {
                    mma_bf16(acc[mi][ni], ah[mi], bh[ni]);
                    mma_bf16(acc[mi][ni], ah[mi], bl[ni]);
                    mma_bf16(acc[mi][ni], al[mi], bh[ni]);
                }
        }
        __syncthreads();
        if (k + 2 < 8) issue(k + 2, stg);
    }
    __syncthreads();

    // stage acc -> smem [n local=128][132] then write transposed [b][n][d]
    float* stage = (float*)dsm;
    #pragma unroll
    for (int mi = 0; mi < 4; mi++) {
        int rl = wm*64 + mi*16 + (lane>>2);
        float bi0 = bias[o0 + rl], bi1 = bias[o0 + rl + 8];
        #pragma unroll
        for (int ni = 0; ni < 4; ni++) {
            int cl = wn*32 + ni*8 + (lane&3)*2;
            float v0 = acc[mi][ni][0] + bi0, v1 = acc[mi][ni][1] + bi0;
            float v2 = acc[mi][ni][2] + bi1, v3 = acc[mi][ni][3] + bi1;
            if (zflag) {
                v0 = __fdividef(1.f, 1.f + __expf(-v0));
                v1 = __fdividef(1.f, 1.f + __expf(-v1));
                v2 = __fdividef(1.f, 1.f + __expf(-v2));
                v3 = __fdividef(1.f, 1.f + __expf(-v3));
            }
            stage[(size_t)cl*132 + rl]         = v0;
            stage[(size_t)(cl+1)*132 + rl]     = v1;
            stage[(size_t)cl*132 + rl + 8]     = v2;
            stage[(size_t)(cl+1)*132 + rl + 8] = v3;
        }
    }
    __syncthreads();
    float* dst = zflag ? g_deltaT : g_x1T;
    for (int idx = tid; idx < 128*128; idx += 256) {
        int n = idx >> 7, dl = idx & 127;
        dst[((size_t)b*NPT + n0 + n)*DI + d0base + dl] = stage[(size_t)n*132 + dl];
    }
}

// ---------------- K2a: conv+silu rolling window -> xs hi/lo bf16 -------------
__global__ void __launch_bounds__(256) k_convz(const float* __restrict__ wconv,
                                               const float* __restrict__ bconv) {
    int b = blockIdx.y, ch = blockIdx.x;
    int d = threadIdx.x;
    int n0 = ch * CL;
    float w0 = wconv[d*4+0], w1 = wconv[d*4+1], w2 = wconv[d*4+2], w3 = wconv[d*4+3];
    float bc = bconv[d];
    const float* src = g_x1T + ((size_t)b*NPT + n0)*DI + d;
    float x3 = 0.f, x2 = 0.f, x1v = 0.f;
    if (n0 > 0) {
        x3  = src[-3*(int)DI];
        x2  = src[-2*(int)DI];
        x1v = src[-(int)DI];
    }
    __nv_bfloat16* xh = g_xshi + ((size_t)b*NPT + n0)*DI + d;
    __nv_bfloat16* xl = g_xslo + ((size_t)b*NPT + n0)*DI + d;
    #pragma unroll 8
    for (int k = 0; k < CL; k++) {
        float x0 = src[(size_t)k*DI];
        float v = fmaf(w3, x0, fmaf(w2, x1v, fmaf(w1, x2, fmaf(w0, x3, bc))));
        float sv = __fdividef(v, 1.f + __expf(-v));
        __nv_bfloat16 hi = __float2bfloat16(sv);
        xh[(size_t)k*DI] = hi;
        xl[(size_t)k*DI] = __float2bfloat16(sv - __bfloat162float(hi));
        x3 = x2; x2 = x1v; x1v = x0;
    }
}

// ---------------- K2b: B/C projection via mma.sync, 3-stage pipeline --------
#define BC_AB (64*SAS*2)
#define BC_BB (32*SAS*2)
#define BC_STG (2*BC_AB + 2*BC_BB)
__global__ void __launch_bounds__(256) k_mma_bc() {
    __shared__ __align__(16) char dsm[3*BC_STG];
    uint32_t sb = smem_u32(dsm);
    int tid = threadIdx.x, lane = tid & 31, wid = tid >> 5;
    int wm = wid & 3, wn = wid >> 2;
    size_t r0 = (size_t)blockIdx.x * 64;

    float acc[2][4];
    #pragma unroll
    for (int i = 0; i < 2; i++)
        #pragma unroll
        for (int q = 0; q < 4; q++) acc[i][q] = 0.f;

    auto issue = [&](int k, int stg) {
        uint32_t sbase = sb + (uint32_t)stg*BC_STG;
        int k0 = k*32;
        #pragma unroll
        for (int i = 0; i < 2; i++) {
            int idx = tid + i*256;
            int arr = idx >> 8, rem = idx & 255;
            int row = rem >> 2, seg = rem & 3;
            uint32_t so = (uint32_t)arr*BC_AB + (uint32_t)((row*SAS + seg*8)*2);
            size_t g = (r0 + row)*DI + k0 + seg*8;
            cpa16(sbase + so, arr ? (const void*)&g_xslo[g] : (const void*)&g_xshi[g]);
        }
        {
            int arr = tid >> 7, rem = tid & 127;
            int row = rem >> 2, seg = rem & 3;
            uint32_t so = 2*BC_AB + (uint32_t)arr*BC_BB + (uint32_t)((row*SAS + seg*8)*2);
            size_t g = (size_t)row*256 + k0 + seg*8;
            cpa16(sbase + so, arr ? (const void*)&g_wbclo[g] : (const void*)&g_wbchi[g]);
        }
        CPA_COMMIT();
    };

    uint32_t aoff = (uint32_t)(((wm*16 + (lane&15))*SAS + (lane>>4)*8) * 2);
    uint32_t boff = 2*BC_AB + (uint32_t)(((wn*16 + (lane&7))*SAS + ((lane>>3)&1)*8) * 2);

    issue(0, 0);
    issue(1, 1);
    issue(2, 2);

    #pragma unroll
    for (int k = 0; k < 8; k++) {
        if (k < 6)       asm volatile("cp.async.wait_group 2;" ::: "memory");
        else if (k == 6) asm volatile("cp.async.wait_group 1;" ::: "memory");
        else             asm volatile("cp.async.wait_group 0;" ::: "memory");
        __syncthreads();
        int stg = k % 3;
        uint32_t aBase = sb + (uint32_t)stg*BC_STG + aoff;
        uint32_t bBase = sb + (uint32_t)stg*BC_STG + boff;
        #pragma unroll
        for (int ks = 0; ks < 2; ks++) {
            uint32_t koff = ks*32;
            uint32_t ah[4], al[4], bh[2][2], bl[2][2];
            ldsm4(ah, aBase + koff);
            ldsm4(al, aBase + BC_AB + koff);
            #pragma unroll
            for (int ni = 0; ni < 2; ni++) {
                ldsm2(bh[ni], bBase + ni*(8*SAS*2) + koff);
                ldsm2(bl[ni], bBase + BC_BB + ni*(8*SAS*2) + koff);
            }
            #pragma unroll
            for (int ni = 0; ni < 2; ni++) {
                mma_bf16(acc[ni], ah, bh[ni]);
                mma_bf16(acc[ni], ah, bl[ni]);
                mma_bf16(acc[ni], al, bh[ni]);
            }
        }
        __syncthreads();
        if (k + 3 < 8) issue(k + 3, stg);
    }

    #pragma unroll
    for (int ni = 0; ni < 2; ni++) {
        int col = wn*16 + ni*8 + (lane&3)*2;
        float* base = (col < 16) ? g_Bm : g_Cm;
        int cb = col & 15;
        size_t row = r0 + wm*16 + (lane>>2);
        *(float2*)&base[row*NS + cb]     = make_float2(acc[ni][0], acc[ni][1]);
        *(float2*)&base[(row+8)*NS + cb] = make_float2(acc[ni][2], acc[ni][3]);
    }
}

// ---------------- K3 (S1): per-chunk local scan -> P ------------------------
__global__ void k_scan1() {
    __shared__ float sB[CL*NS];
    int b = blockIdx.y, ch = blockIdx.x;
    int tid = threadIdx.x;
    int t0 = ch * CL;
    for (int i = tid; i < CL*NS; i += 256)
        sB[i] = g_Bm[((size_t)b*NPT + t0)*NS + i];
    __syncthreads();
    float A[NS], h[NS];
    #pragma unroll
    for (int s = 0; s < NS; s++) { A[s] = g_A[tid*NS + s]; h[s] = 0.f; }
    const float* dptr = g_deltaT + ((size_t)b*NPT + t0)*DI + tid;
    for (int k = 0; k < CL; k++) {
        float dl = dptr[(size_t)k*DI];
        const float* Bk = &sB[k*NS];
        #pragma unroll
        for (int s = 0; s < NS; s++)
            h[s] = fmaf(A[s], h[s], dl * Bk[s]);
    }
    float* P = g_P + ((size_t)b*NC + ch)*NS*DI + tid;
    #pragma unroll
    for (int s = 0; s < NS; s++) P[s*DI] = h[s];
}

// ---------------- K4 (S2): inter-chunk prefix --------------------------------
__global__ void k_scan2() {
    int g = blockIdx.x * 256 + threadIdx.x;
    int d = g & 255;
    int s = (g >> 8) & 15;
    int b = g >> 12;
    float aL = g_aL[d*NS + s];
    float h = 0.f;
    size_t base = ((size_t)b*NC*NS + s)*DI + d;
    for (int c = 0; c < NC; c++) {
        size_t idx = base + (size_t)c*NS*DI;
        g_H0[idx] = h;
        h = fmaf(aL, h, g_P[idx]);
    }
}

// ---------------- K5 (S3): final scan + y hi/lo bf16 -------------------------
__global__ void k_scan3(const float* __restrict__ Dskip) {
    __shared__ float sB[CL*NS], sC[CL*NS];
    int b = blockIdx.y, ch = blockIdx.x;
    int tid = threadIdx.x;
    int t0 = ch * CL;
    for (int i = tid; i < CL*NS; i += 256) {
        sB[i] = g_Bm[((size_t)b*NPT + t0)*NS + i];
        sC[i] = g_Cm[((size_t)b*NPT + t0)*NS + i];
    }
    __syncthreads();
    float A[NS], h[NS];
    size_t hbase = ((size_t)b*NC + ch)*NS*DI + tid;
    #pragma unroll
    for (int s = 0; s < NS; s++) { A[s] = g_A[tid*NS + s]; h[s] = g_H0[hbase + s*DI]; }
    float dsk = Dskip[tid];
    const float* dptr = g_deltaT + ((size_t)b*NPT + t0)*DI + tid;
    const __nv_bfloat16* xhp = g_xshi + ((size_t)b*NPT + t0)*DI + tid;
    const __nv_bfloat16* xlp = g_xslo + ((size_t)b*NPT + t0)*DI + tid;
    __nv_bfloat16* yh = g_yhi + ((size_t)b*NPT + t0)*DI + tid;
    __nv_bfloat16* yl = g_ylo + ((size_t)b*NPT + t0)*DI + tid;
    for (int k = 0; k < CL; k++) {
        float dl = dptr[(size_t)k*DI];
        float xv = __bfloat162float(xhp[(size_t)k*DI]) + __bfloat162float(xlp[(size_t)k*DI]);
        const float* Bk = &sB[k*NS];
        const float* Ck = &sC[k*NS];
        float y = dsk * xv;
        #pragma unroll
        for (int s = 0; s < NS; s++) {
            h[s] = fmaf(A[s], h[s], dl * Bk[s]);
            y = fmaf(h[s], Ck[s], y);
        }
        __nv_bfloat16 hi = __float2bfloat16(y);
        yh[(size_t)k*DI] = hi;
        yl[(size_t)k*DI] = __float2bfloat16(y - __bfloat162float(hi));
    }
}

// ---------------- K6: fused out_proj + bias + residual + LN + store ----------
#define OL_A_B (128*SAS*2)
#define OL_B_B (256*SAS*2)
#define OL_STG (2*OL_A_B + 2*OL_B_B)
#define OL_XB  32768
#define OL_EPI (256*36*4 + 256 + 2*OL_XB)
#define OL_DSM ((2*OL_STG) > OL_EPI ? (2*OL_STG) : OL_EPI)
__global__ void __launch_bounds__(512) k_mma_out_ln(
    const float* __restrict__ x, const float* __restrict__ bout,
    const float* __restrict__ gamma, const float* __restrict__ beta,
    float* __restrict__ out) {
    extern __shared__ char dsm[];
    uint32_t sb = smem_u32(dsm);
    int tid = threadIdx.x, lane = tid & 31, wid = tid >> 5;
    int wm = wid & 3, wn = wid >> 2;
    size_t r0 = (size_t)blockIdx.x * 128;
    int b = (int)(r0 >> 12);
    int n0 = (int)(r0 & 4095);

    float acc[2][8][4];
    #pragma unroll
    for (int i = 0; i < 2; i++)
        #pragma unroll
        for (int j = 0; j < 8; j++)
            #pragma unroll
            for (int q = 0; q < 4; q++) acc[i][j][q] = 0.f;

    auto issue = [&](int k, int stg) {
        uint32_t sbase = sb + (uint32_t)stg*OL_STG;
        int k0 = k*32;
        #pragma unroll
        for (int i = 0; i < 2; i++) {
            int idx = tid + i*512;
            int arr = idx >> 9, rem = idx & 511;
            int row = rem >> 2, seg = rem & 3;
            uint32_t so = (uint32_t)arr*OL_A_B + (uint32_t)((row*SAS + seg*8)*2);
            size_t g = (r0 + row)*DI + k0 + seg*8;
            cpa16(sbase + so, arr ? (const void*)&g_ylo[g] : (const void*)&g_yhi[g]);
        }
        #pragma unroll
        for (int i = 0; i < 4; i++) {
            int idx = tid + i*512;
            int arr = idx >> 10, rem = idx & 1023;
            int row = rem >> 2, seg = rem & 3;
            uint32_t so = 2*OL_A_B + (uint32_t)arr*OL_B_B + (uint32_t)((row*SAS + seg*8)*2);
            size_t g = (size_t)row*DI + k0 + seg*8;
            cpa16(sbase + so, arr ? (const void*)&g_wolo[g] : (const void*)&g_wohi[g]);
        }
        CPA_COMMIT();
    };

    uint32_t aoff = (uint32_t)(((wm*32 + (lane&15))*SAS + (lane>>4)*8) * 2);
    uint32_t boff = 2*OL_A_B + (uint32_t)(((wn*64 + (lane&7))*SAS + ((lane>>3)&1)*8) * 2);

    issue(0, 0);
    issue(1, 1);

    #pragma unroll
    for (int k = 0; k < 8; k++) {
        if (k < 7) asm volatile("cp.async.wait_group 1;" ::: "memory");
        else       asm volatile("cp.async.wait_group 0;" ::: "memory");
        __syncthreads();
        int stg = k & 1;
        uint32_t aBase = sb + (uint32_t)stg*OL_STG + aoff;
        uint32_t bBase = sb + (uint32_t)stg*OL_STG + boff;
        #pragma unroll
        for (int ks = 0; ks < 2; ks++) {
            uint32_t koff = ks*32;
            uint32_t ah[2][4], al[2][4], bh[8][2], bl[8][2];
            #pragma unroll
            for (int mi = 0; mi < 2; mi++) {
                ldsm4(ah[mi], aBase + mi*(16*SAS*2) + koff);
                ldsm4(al[mi], aBase + OL_A_B + mi*(16*SAS*2) + koff);
            }
            #pragma unroll
            for (int ni = 0; ni < 8; ni++) {
                ldsm2(bh[ni], bBase + ni*(8*SAS*2) + koff);
                ldsm2(bl[ni], bBase + OL_B_B + ni*(8*SAS*2) + koff);
            }
            #pragma unroll
            for (int mi = 0; mi < 2; mi++)
                #pragma unroll
                for (int ni = 0; ni < 8; ni++) {
                    mma_bf16(acc[mi][ni], ah[mi], bh[ni]);
                    mma_bf16(acc[mi][ni], ah[mi], bl[ni]);
                    mma_bf16(acc[mi][ni], al[mi], bh[ni]);
                }
        }
        __syncthreads();
        if (k + 2 < 8) issue(k + 2, stg);
    }
    __syncthreads();

    float* stage = (float*)dsm;
    float* mu = (float*)(dsm + 256*36*4);
    float* rs = mu + 32;
    uint32_t xb_base = sb + 256*36*4 + 256;
    float* xb_ptr = (float*)(dsm + 256*36*4 + 256);

    auto issue_x = [&](int p) {
        uint32_t dst = xb_base + (uint32_t)(p & 1)*OL_XB;
        int nb = n0 + p*32;
        #pragma unroll
        for (int i = 0; i < 4; i++) {
            int idx = tid + i*512;
            int c = idx >> 3, seg = idx & 7;
            cpa16(dst + (uint32_t)(c*32 + seg*4)*4,
                  &x[((size_t)b*DIMC + c)*NPT + nb + seg*4]);
        }
        CPA_COMMIT();
    };

    issue_x(0);
    for (int p = 0; p < 4; p++) {
        if (p + 1 < 4) issue_x(p + 1);
        if (wm == p) {
            #pragma unroll
            for (int mi = 0; mi < 2; mi++) {
                int rl = mi*16 + (lane>>2);
                #pragma unroll
                for (int ni = 0; ni < 8; ni++) {
                    int c = wn*64 + ni*8 + (lane&3)*2;
                    float b0 = bout[c], b1 = bout[c+1];
                    stage[(size_t)c*36 + rl]         = acc[mi][ni][0] + b0;
                    stage[(size_t)(c+1)*36 + rl]     = acc[mi][ni][1] + b1;
                    stage[(size_t)c*36 + rl + 8]     = acc[mi][ni][2] + b0;
                    stage[(size_t)(c+1)*36 + rl + 8] = acc[mi][ni][3] + b1;
                }
            }
        }
        if (p + 1 < 4) asm volatile("cp.async.wait_group 1;" ::: "memory");
        else           asm volatile("cp.async.wait_group 0;" ::: "memory");
        __syncthreads();
        float* xb = xb_ptr + (p & 1)*(OL_XB/4);
        for (int idx = tid; idx < 8192; idx += 512) {
            int c = idx >> 5, nn = idx & 31;
            stage[(size_t)c*36 + nn] += xb[c*32 + nn];
        }
        __syncthreads();
        {
            int nn = wid*2 + (lane>>4);
            int h = lane & 15;
            float sum = 0.f, sq = 0.f;
            #pragma unroll
            for (int c = h; c < 256; c += 16) {
                float v = stage[(size_t)c*36 + nn];
                sum += v; sq += v*v;
            }
            #pragma unroll
            for (int o = 1; o < 16; o <<= 1) {
                sum += __shfl_xor_sync(0xFFFFFFFFu, sum, o);
                sq  += __shfl_xor_sync(0xFFFFFFFFu, sq,  o);
            }
            if (h == 0) {
                float m = sum * (1.f/256.f);
                mu[nn] = m;
                rs[nn] = rsqrtf(sq * (1.f/256.f) - m*m + 1e-5f);
            }
        }
        __syncthreads();
        int nb = n0 + p*32;
        for (int idx = tid; idx < 8192; idx += 512) {
            int c = idx >> 5, nn = idx & 31;
            float v = (stage[(size_t)c*36 + nn] - mu[nn]) * rs[nn] * gamma[c] + beta[c];
            out[((size_t)b*DIMC + c)*NPT + nb + nn] = v;
        }
        __syncthreads();
    }
}

// ---------------- launch: stream fork/join (graph-capturable) ----------------
extern "C" void kernel_launch(void* const* d_in, const int* in_sizes, int n_in,
                              void* d_out, int out_size) {
    const float* x      = (const float*)d_in[0];
    const float* w_in   = (const float*)d_in[1];
    const float* b_in   = (const float*)d_in[2];
    const float* w_conv = (const float*)d_in[3];
    const float* b_conv = (const float*)d_in[4];
    const float* A_log  = (const float*)d_in[5];
    const float* D_skip = (const float*)d_in[6];
    const float* Bw     = (const float*)d_in[7];
    const float* Cw     = (const float*)d_in[8];
    const float* w_out  = (const float*)d_in[9];
    const float* b_out  = (const float*)d_in[10];
    const float* gamma  = (const float*)d_in[11];
    const float* beta   = (const float*)d_in[12];
    float* out = (float*)d_out;

    cudaFuncSetAttribute(k_mma_in,     cudaFuncAttributeMaxDynamicSharedMemorySize, MMA_DSM);
    cudaFuncSetAttribute(k_mma_out_ln, cudaFuncAttributeMaxDynamicSharedMemorySize, OL_DSM);

    // per-call stream+events (host objects, not device memory; not destroyed
    // mid-capture — kernel_launch is only invoked a handful of times)
    cudaStream_t s2;
    cudaEvent_t eFork, eJoin;
    cudaStreamCreateWithFlags(&s2, cudaStreamNonBlocking);
    cudaEventCreateWithFlags(&eFork, cudaEventDisableTiming);
    cudaEventCreateWithFlags(&eJoin, cudaEventDisableTiming);

    k_prep<<<816 + 2048, 256>>>(A_log, w_in, w_out, Bw, Cw, x);

    cudaEventRecord(eFork, 0);
    cudaStreamWaitEvent(s2, eFork, 0);
    // branch B (worker stream): z-half GEMM -> deltaT
    k_mma_in<<<dim3(32, 2, BATCH), 256, MMA_DSM, s2>>>(b_in, 1);
    // branch A (main stream): x1-half GEMM -> conv -> B/C projection
    k_mma_in<<<dim3(32, 2, BATCH), 256, MMA_DSM>>>(b_in, 0);
    k_convz<<<dim3(NC, BATCH), 256>>>(w_conv, b_conv);
    k_mma_bc<<<256, 256>>>();
    // join
    cudaEventRecord(eJoin, s2);
    cudaStreamWaitEvent(0, eJoin, 0);

    k_scan1<<<dim3(NC, BATCH), 256>>>();
    k_scan2<<<64, 256>>>();
    k_scan3<<<dim3(NC, BATCH), 256>>>(D_skip);
    k_mma_out_ln<<<128, 512, OL_DSM>>>(x, b_out, gamma, beta, out);
}

// round 17
// speedup vs baseline: 1.0361x; 1.0361x over previous
#include <cuda_runtime.h>
#include <cuda_bf16.h>
#include <math.h>
#include <stdint.h>

#define BATCH 4
#define DIMC  256
#define DI    256
#define NS    16
#define NPT   4096
#define NC    64
#define CL    64

// ---- mma.sync + cp.async helpers ----
__device__ __forceinline__ uint32_t smem_u32(const void* p) {
    uint32_t a; asm("{ .reg .u64 t; cvta.to.shared.u64 t, %1; cvt.u32.u64 %0, t; }" : "=r"(a) : "l"(p));
    return a;
}
__device__ __forceinline__ void mma_bf16(float* c, const uint32_t* a, const uint32_t* b) {
    asm volatile(
        "mma.sync.aligned.m16n8k16.row.col.f32.bf16.bf16.f32 "
        "{%0,%1,%2,%3}, {%4,%5,%6,%7}, {%8,%9}, {%0,%1,%2,%3};"
        : "+f"(c[0]), "+f"(c[1]), "+f"(c[2]), "+f"(c[3])
        : "r"(a[0]), "r"(a[1]), "r"(a[2]), "r"(a[3]), "r"(b[0]), "r"(b[1]));
}
__device__ __forceinline__ void ldsm4(uint32_t* r, uint32_t addr) {
    asm volatile("ldmatrix.sync.aligned.m8n8.x4.shared.b16 {%0,%1,%2,%3}, [%4];"
        : "=r"(r[0]), "=r"(r[1]), "=r"(r[2]), "=r"(r[3]) : "r"(addr));
}
__device__ __forceinline__ void ldsm2(uint32_t* r, uint32_t addr) {
    asm volatile("ldmatrix.sync.aligned.m8n8.x2.shared.b16 {%0,%1}, [%2];"
        : "=r"(r[0]), "=r"(r[1]) : "r"(addr));
}
__device__ __forceinline__ void cpa16(uint32_t s, const void* g) {
    asm volatile("cp.async.cg.shared.global [%0], [%1], 16;"
        :: "r"(s), "l"(__cvta_generic_to_global(g)));
}
#define CPA_COMMIT() asm volatile("cp.async.commit_group;" ::: "memory")

// ---------------- scratch (device globals) ----------------
static __device__ float g_x1T[BATCH*NPT*DI];        // in_proj x1 half, TRANSPOSED [b][n][d]
static __device__ float g_deltaT[BATCH*NPT*DI];
static __device__ float g_Bm[BATCH*NPT*NS];
static __device__ float g_Cm[BATCH*NPT*NS];
static __device__ float g_P[BATCH*NC*NS*DI];
static __device__ float g_H0[BATCH*NC*NS*DI];
static __device__ float g_A[DI*NS];
static __device__ float g_aL[DI*NS];
static __device__ __nv_bfloat16 g_whi[512*256];
static __device__ __nv_bfloat16 g_wlo[512*256];
static __device__ __nv_bfloat16 g_wohi[256*256];
static __device__ __nv_bfloat16 g_wolo[256*256];
static __device__ __nv_bfloat16 g_wbchi[32*256];
static __device__ __nv_bfloat16 g_wbclo[32*256];
static __device__ __nv_bfloat16 g_xthi[BATCH*NPT*DIMC];  // [b][n][c]
static __device__ __nv_bfloat16 g_xtlo[BATCH*NPT*DIMC];
static __device__ __nv_bfloat16 g_xshi[BATCH*NPT*DI];    // silu(conv) [b][n][d]
static __device__ __nv_bfloat16 g_xslo[BATCH*NPT*DI];
static __device__ __nv_bfloat16 g_yhi[BATCH*NPT*DI];     // [b][n][d]
static __device__ __nv_bfloat16 g_ylo[BATCH*NPT*DI];

// ---------------- K-prep ------------------------------------------------------
__global__ void k_prep(const float* __restrict__ A_log, const float* __restrict__ w_in,
                       const float* __restrict__ w_out, const float* __restrict__ Bw,
                       const float* __restrict__ Cw, const float* __restrict__ x) {
    int blk = blockIdx.x, tid = threadIdx.x;
    if (blk < 512) {
        int i = blk*256 + tid;
        float v = w_in[i];
        __nv_bfloat16 hi = __float2bfloat16(v);
        g_whi[i] = hi;
        g_wlo[i] = __float2bfloat16(v - __bfloat162float(hi));
    } else if (blk < 768) {
        int i = (blk-512)*256 + tid;
        float v = w_out[i];
        __nv_bfloat16 hi = __float2bfloat16(v);
        g_wohi[i] = hi;
        g_wolo[i] = __float2bfloat16(v - __bfloat162float(hi));
    } else if (blk < 784) {
        int i = (blk-768)*256 + tid;
        if (i < DI*NS) {
            float al = A_log[i];
            g_A[i]  = -expf(al);
            g_aL[i] =  expf((float)CL * al);   // CL even
        }
    } else if (blk < 816) {
        int i = (blk-784)*256 + tid;
        float v = (i < 4096) ? Bw[i] : Cw[i - 4096];
        __nv_bfloat16 hi = __float2bfloat16(v);
        g_wbchi[i] = hi;
        g_wbclo[i] = __float2bfloat16(v - __bfloat162float(hi));
    } else {
        __shared__ float s[64][33];
        int t = blk - 816;                 // 0..2047
        int b = t >> 9, rem = t & 511;
        int ct = rem >> 7, nt = rem & 127; // 4 c-tiles x 128 n-tiles
        int c0 = ct*64, n0 = nt*32;
        int tx = tid & 31, ty = tid >> 5;
        #pragma unroll
        for (int i = 0; i < 64; i += 8)
            s[ty+i][tx] = x[((size_t)b*DIMC + c0+ty+i)*NPT + n0 + tx];
        __syncthreads();
        #pragma unroll
        for (int j = 0; j < 4; j++) {
            int n = ty + j*8;
            int c = tx*2;
            float v0 = s[c][n], v1 = s[c+1][n];
            __nv_bfloat16 h0 = __float2bfloat16(v0), h1 = __float2bfloat16(v1);
            __nv_bfloat16 l0 = __float2bfloat16(v0 - __bfloat162float(h0));
            __nv_bfloat16 l1 = __float2bfloat16(v1 - __bfloat162float(h1));
            size_t idx = ((size_t)b*NPT + n0+n)*DIMC + c0 + c;
            __nv_bfloat162 hh; hh.x = h0; hh.y = h1;
            __nv_bfloat162 ll; ll.x = l0; ll.y = l1;
            *(__nv_bfloat162*)&g_xthi[idx] = hh;
            *(__nv_bfloat162*)&g_xtlo[idx] = ll;
        }
    }
}

// ---------------- K1: in_proj mma.sync; both halves write transposed ---------
#define SAS 40
#define ARR_B (128*SAS*2)
#define STG_B (4*ARR_B)
#define MMA_DSM (2*STG_B)
__global__ void __launch_bounds__(256) k_mma_in(const float* __restrict__ bias) {
    extern __shared__ char dsm[];
    uint32_t sb = smem_u32(dsm);
    int tid = threadIdx.x, lane = tid & 31, wid = tid >> 5;
    int wm = wid & 1, wn = wid >> 1;
    int nt = blockIdx.x, mt = blockIdx.y, b = blockIdx.z;
    int o0 = mt*128, n0 = nt*128;

    float acc[4][4][4];
    #pragma unroll
    for (int i = 0; i < 4; i++)
        #pragma unroll
        for (int j = 0; j < 4; j++)
            #pragma unroll
            for (int q = 0; q < 4; q++) acc[i][j][q] = 0.f;

    auto issue = [&](int k, int stg) {
        uint32_t sbase = sb + (uint32_t)stg*STG_B;
        int k0 = k*32;
        #pragma unroll
        for (int i = 0; i < 2; i++) {
            int idx = tid + i*256;
            int row = idx >> 2, seg = idx & 3;
            uint32_t so = (uint32_t)((row*SAS + seg*8)*2);
            size_t ga = (size_t)(o0 + row)*256 + k0 + seg*8;
            size_t gb = ((size_t)b*NPT + n0 + row)*DIMC + k0 + seg*8;
            cpa16(sbase + so,             &g_whi[ga]);
            cpa16(sbase + ARR_B + so,     &g_wlo[ga]);
            cpa16(sbase + 2*ARR_B + so,   &g_xthi[gb]);
            cpa16(sbase + 3*ARR_B + so,   &g_xtlo[gb]);
        }
        CPA_COMMIT();
    };

    uint32_t aoff = (uint32_t)(((wm*64 + (lane&15))*SAS + (lane>>4)*8) * 2);
    uint32_t boff = (uint32_t)(((wn*32 + (lane&7))*SAS + ((lane>>3)&1)*8) * 2);

    issue(0, 0);
    issue(1, 1);

    #pragma unroll
    for (int k = 0; k < 8; k++) {
        if (k < 7) asm volatile("cp.async.wait_group 1;" ::: "memory");
        else       asm volatile("cp.async.wait_group 0;" ::: "memory");
        __syncthreads();
        int stg = k & 1;
        uint32_t aBase = sb + (uint32_t)stg*STG_B + aoff;
        uint32_t bBase = sb + (uint32_t)stg*STG_B + 2*ARR_B + boff;
        #pragma unroll
        for (int ks = 0; ks < 2; ks++) {
            uint32_t koff = ks*32;
            uint32_t ah[4][4], al[4][4], bh[4][2], bl[4][2];
            #pragma unroll
            for (int mi = 0; mi < 4; mi++) {
                ldsm4(ah[mi], aBase + mi*(16*SAS*2) + koff);
                ldsm4(al[mi], aBase + ARR_B + mi*(16*SAS*2) + koff);
            }
            #pragma unroll
            for (int ni = 0; ni < 4; ni++) {
                ldsm2(bh[ni], bBase + ni*(8*SAS*2) + koff);
                ldsm2(bl[ni], bBase + ARR_B + ni*(8*SAS*2) + koff);
            }
            #pragma unroll
            for (int mi = 0; mi < 4; mi++)
                #pragma unroll
                for (int ni = 0; ni < 4; ni++) {
                    mma_bf16(acc[mi][ni], ah[mi], bh[ni]);
                    mma_bf16(acc[mi][ni], ah[mi], bl[ni]);
                    mma_bf16(acc[mi][ni], al[mi], bh[ni]);
                }
        }
        __syncthreads();
        if (k + 2 < 8) issue(k + 2, stg);
    }
    __syncthreads();

    // stage acc -> smem [n local=128][132] then write transposed [b][n][d]
    float* stage = (float*)dsm;
    bool is_z = (mt >= 2);
    int d0base = is_z ? (mt - 2) * 128 : o0;
    #pragma unroll
    for (int mi = 0; mi < 4; mi++) {
        int rl = wm*64 + mi*16 + (lane>>2);
        float bi0 = bias[o0 + rl], bi1 = bias[o0 + rl + 8];
        #pragma unroll
        for (int ni = 0; ni < 4; ni++) {
            int cl = wn*32 + ni*8 + (lane&3)*2;
            float v0 = acc[mi][ni][0] + bi0, v1 = acc[mi][ni][1] + bi0;
            float v2 = acc[mi][ni][2] + bi1, v3 = acc[mi][ni][3] + bi1;
            if (is_z) {
                v0 = __fdividef(1.f, 1.f + __expf(-v0));
                v1 = __fdividef(1.f, 1.f + __expf(-v1));
                v2 = __fdividef(1.f, 1.f + __expf(-v2));
                v3 = __fdividef(1.f, 1.f + __expf(-v3));
            }
            stage[(size_t)cl*132 + rl]         = v0;
            stage[(size_t)(cl+1)*132 + rl]     = v1;
            stage[(size_t)cl*132 + rl + 8]     = v2;
            stage[(size_t)(cl+1)*132 + rl + 8] = v3;
        }
    }
    __syncthreads();
    float* dst = is_z ? g_deltaT : g_x1T;
    for (int idx = tid; idx < 128*128; idx += 256) {
        int n = idx >> 7, dl = idx & 127;
        dst[((size_t)b*NPT + n0 + n)*DI + d0base + dl] = stage[(size_t)n*132 + dl];
    }
}

// ---------------- K2a: TILED conv+silu on [n][d] layout -> xs hi/lo ----------
// Block: 64 n x 64 d, smem tile with 3-row causal halo. All loads before one
// sync (full MLP), conflict-free smem reads, coalesced stores.
__global__ void __launch_bounds__(256) k_convz(const float* __restrict__ wconv,
                                               const float* __restrict__ bconv) {
    __shared__ float s[67*64];
    int b = blockIdx.z, dt = blockIdx.y, nt = blockIdx.x;
    int d0 = dt*64, n0 = nt*64;
    int tid = threadIdx.x;

    for (int i = tid; i < 67*64; i += 256) {
        int r = i >> 6, dd = i & 63;
        int n = n0 - 3 + r;
        s[i] = (n >= 0) ? g_x1T[((size_t)b*NPT + n)*DI + d0 + dd] : 0.f;
    }
    __syncthreads();

    int dd = tid & 63, tg = tid >> 6;     // 64 d-lanes x 4 n-groups
    int d = d0 + dd;
    float w0 = wconv[d*4+0], w1 = wconv[d*4+1], w2 = wconv[d*4+2], w3 = wconv[d*4+3];
    float bc = bconv[d];
    __nv_bfloat16* xh = g_xshi + ((size_t)b*NPT + n0)*DI + d;
    __nv_bfloat16* xl = g_xslo + ((size_t)b*NPT + n0)*DI + d;
    #pragma unroll 4
    for (int j = 0; j < 16; j++) {
        int n = tg*16 + j;
        const float* r = &s[n*64 + dd];
        float v = fmaf(w3, r[3*64], fmaf(w2, r[2*64], fmaf(w1, r[64], fmaf(w0, r[0], bc))));
        float sv = __fdividef(v, 1.f + __expf(-v));
        __nv_bfloat16 hi = __float2bfloat16(sv);
        xh[(size_t)n*DI] = hi;
        xl[(size_t)n*DI] = __float2bfloat16(sv - __bfloat162float(hi));
    }
}

// ---------------- K2b: B/C projection via mma.sync, 3-stage pipeline --------
#define BC_AB (64*SAS*2)
#define BC_BB (32*SAS*2)
#define BC_STG (2*BC_AB + 2*BC_BB)
__global__ void __launch_bounds__(256) k_mma_bc() {
    __shared__ __align__(16) char dsm[3*BC_STG];
    uint32_t sb = smem_u32(dsm);
    int tid = threadIdx.x, lane = tid & 31, wid = tid >> 5;
    int wm = wid & 3, wn = wid >> 2;
    size_t r0 = (size_t)blockIdx.x * 64;

    float acc[2][4];
    #pragma unroll
    for (int i = 0; i < 2; i++)
        #pragma unroll
        for (int q = 0; q < 4; q++) acc[i][q] = 0.f;

    auto issue = [&](int k, int stg) {
        uint32_t sbase = sb + (uint32_t)stg*BC_STG;
        int k0 = k*32;
        #pragma unroll
        for (int i = 0; i < 2; i++) {
            int idx = tid + i*256;
            int arr = idx >> 8, rem = idx & 255;
            int row = rem >> 2, seg = rem & 3;
            uint32_t so = (uint32_t)arr*BC_AB + (uint32_t)((row*SAS + seg*8)*2);
            size_t g = (r0 + row)*DI + k0 + seg*8;
            cpa16(sbase + so, arr ? (const void*)&g_xslo[g] : (const void*)&g_xshi[g]);
        }
        {
            int arr = tid >> 7, rem = tid & 127;
            int row = rem >> 2, seg = rem & 3;
            uint32_t so = 2*BC_AB + (uint32_t)arr*BC_BB + (uint32_t)((row*SAS + seg*8)*2);
            size_t g = (size_t)row*256 + k0 + seg*8;
            cpa16(sbase + so, arr ? (const void*)&g_wbclo[g] : (const void*)&g_wbchi[g]);
        }
        CPA_COMMIT();
    };

    uint32_t aoff = (uint32_t)(((wm*16 + (lane&15))*SAS + (lane>>4)*8) * 2);
    uint32_t boff = 2*BC_AB + (uint32_t)(((wn*16 + (lane&7))*SAS + ((lane>>3)&1)*8) * 2);

    issue(0, 0);
    issue(1, 1);
    issue(2, 2);

    #pragma unroll
    for (int k = 0; k < 8; k++) {
        if (k < 6)       asm volatile("cp.async.wait_group 2;" ::: "memory");
        else if (k == 6) asm volatile("cp.async.wait_group 1;" ::: "memory");
        else             asm volatile("cp.async.wait_group 0;" ::: "memory");
        __syncthreads();
        int stg = k % 3;
        uint32_t aBase = sb + (uint32_t)stg*BC_STG + aoff;
        uint32_t bBase = sb + (uint32_t)stg*BC_STG + boff;
        #pragma unroll
        for (int ks = 0; ks < 2; ks++) {
            uint32_t koff = ks*32;
            uint32_t ah[4], al[4], bh[2][2], bl[2][2];
            ldsm4(ah, aBase + koff);
            ldsm4(al, aBase + BC_AB + koff);
            #pragma unroll
            for (int ni = 0; ni < 2; ni++) {
                ldsm2(bh[ni], bBase + ni*(8*SAS*2) + koff);
                ldsm2(bl[ni], bBase + BC_BB + ni*(8*SAS*2) + koff);
            }
            #pragma unroll
            for (int ni = 0; ni < 2; ni++) {
                mma_bf16(acc[ni], ah, bh[ni]);
                mma_bf16(acc[ni], ah, bl[ni]);
                mma_bf16(acc[ni], al, bh[ni]);
            }
        }
        __syncthreads();
        if (k + 3 < 8) issue(k + 3, stg);
    }

    #pragma unroll
    for (int ni = 0; ni < 2; ni++) {
        int col = wn*16 + ni*8 + (lane&3)*2;
        float* base = (col < 16) ? g_Bm : g_Cm;
        int cb = col & 15;
        size_t row = r0 + wm*16 + (lane>>2);
        *(float2*)&base[row*NS + cb]     = make_float2(acc[ni][0], acc[ni][1]);
        *(float2*)&base[(row+8)*NS + cb] = make_float2(acc[ni][2], acc[ni][3]);
    }
}

// ---------------- K3 (S1): per-chunk local scan -> P ------------------------
__global__ void k_scan1() {
    __shared__ float sB[CL*NS];
    int b = blockIdx.y, ch = blockIdx.x;
    int tid = threadIdx.x;
    int t0 = ch * CL;
    for (int i = tid; i < CL*NS; i += 256)
        sB[i] = g_Bm[((size_t)b*NPT + t0)*NS + i];
    __syncthreads();
    float A[NS], h[NS];
    #pragma unroll
    for (int s = 0; s < NS; s++) { A[s] = g_A[tid*NS + s]; h[s] = 0.f; }
    const float* dptr = g_deltaT + ((size_t)b*NPT + t0)*DI + tid;
    for (int k = 0; k < CL; k++) {
        float dl = dptr[(size_t)k*DI];
        const float* Bk = &sB[k*NS];
        #pragma unroll
        for (int s = 0; s < NS; s++)
            h[s] = fmaf(A[s], h[s], dl * Bk[s]);
    }
    float* P = g_P + ((size_t)b*NC + ch)*NS*DI + tid;
    #pragma unroll
    for (int s = 0; s < NS; s++) P[s*DI] = h[s];
}

// ---------------- K4 (S2): inter-chunk prefix --------------------------------
__global__ void k_scan2() {
    int g = blockIdx.x * 256 + threadIdx.x;
    int d = g & 255;
    int s = (g >> 8) & 15;
    int b = g >> 12;
    float aL = g_aL[d*NS + s];
    float h = 0.f;
    size_t base = ((size_t)b*NC*NS + s)*DI + d;
    for (int c = 0; c < NC; c++) {
        size_t idx = base + (size_t)c*NS*DI;
        g_H0[idx] = h;
        h = fmaf(aL, h, g_P[idx]);
    }
}

// ---------------- K5 (S3): final scan + y hi/lo bf16 -------------------------
__global__ void k_scan3(const float* __restrict__ Dskip) {
    __shared__ float sB[CL*NS], sC[CL*NS];
    int b = blockIdx.y, ch = blockIdx.x;
    int tid = threadIdx.x;
    int t0 = ch * CL;
    for (int i = tid; i < CL*NS; i += 256) {
        sB[i] = g_Bm[((size_t)b*NPT + t0)*NS + i];
        sC[i] = g_Cm[((size_t)b*NPT + t0)*NS + i];
    }
    __syncthreads();
    float A[NS], h[NS];
    size_t hbase = ((size_t)b*NC + ch)*NS*DI + tid;
    #pragma unroll
    for (int s = 0; s < NS; s++) { A[s] = g_A[tid*NS + s]; h[s] = g_H0[hbase + s*DI]; }
    float dsk = Dskip[tid];
    const float* dptr = g_deltaT + ((size_t)b*NPT + t0)*DI + tid;
    const __nv_bfloat16* xhp = g_xshi + ((size_t)b*NPT + t0)*DI + tid;
    const __nv_bfloat16* xlp = g_xslo + ((size_t)b*NPT + t0)*DI + tid;
    __nv_bfloat16* yh = g_yhi + ((size_t)b*NPT + t0)*DI + tid;
    __nv_bfloat16* yl = g_ylo + ((size_t)b*NPT + t0)*DI + tid;
    for (int k = 0; k < CL; k++) {
        float dl = dptr[(size_t)k*DI];
        float xv = __bfloat162float(xhp[(size_t)k*DI]) + __bfloat162float(xlp[(size_t)k*DI]);
        const float* Bk = &sB[k*NS];
        const float* Ck = &sC[k*NS];
        float y = dsk * xv;
        #pragma unroll
        for (int s = 0; s < NS; s++) {
            h[s] = fmaf(A[s], h[s], dl * Bk[s]);
            y = fmaf(h[s], Ck[s], y);
        }
        __nv_bfloat16 hi = __float2bfloat16(y);
        yh[(size_t)k*DI] = hi;
        yl[(size_t)k*DI] = __float2bfloat16(y - __bfloat162float(hi));
    }
}

// ---------------- K6: fused out_proj + bias + residual + LN + store ----------
#define OL_A_B (128*SAS*2)
#define OL_B_B (256*SAS*2)
#define OL_STG (2*OL_A_B + 2*OL_B_B)
#define OL_XB  32768
#define OL_EPI (256*36*4 + 256 + 2*OL_XB)
#define OL_DSM ((2*OL_STG) > OL_EPI ? (2*OL_STG) : OL_EPI)
__global__ void __launch_bounds__(512) k_mma_out_ln(
    const float* __restrict__ x, const float* __restrict__ bout,
    const float* __restrict__ gamma, const float* __restrict__ beta,
    float* __restrict__ out) {
    extern __shared__ char dsm[];
    uint32_t sb = smem_u32(dsm);
    int tid = threadIdx.x, lane = tid & 31, wid = tid >> 5;
    int wm = wid & 3, wn = wid >> 2;
    size_t r0 = (size_t)blockIdx.x * 128;
    int b = (int)(r0 >> 12);
    int n0 = (int)(r0 & 4095);

    float acc[2][8][4];
    #pragma unroll
    for (int i = 0; i < 2; i++)
        #pragma unroll
        for (int j = 0; j < 8; j++)
            #pragma unroll
            for (int q = 0; q < 4; q++) acc[i][j][q] = 0.f;

    auto issue = [&](int k, int stg) {
        uint32_t sbase = sb + (uint32_t)stg*OL_STG;
        int k0 = k*32;
        #pragma unroll
        for (int i = 0; i < 2; i++) {
            int idx = tid + i*512;
            int arr = idx >> 9, rem = idx & 511;
            int row = rem >> 2, seg = rem & 3;
            uint32_t so = (uint32_t)arr*OL_A_B + (uint32_t)((row*SAS + seg*8)*2);
            size_t g = (r0 + row)*DI + k0 + seg*8;
            cpa16(sbase + so, arr ? (const void*)&g_ylo[g] : (const void*)&g_yhi[g]);
        }
        #pragma unroll
        for (int i = 0; i < 4; i++) {
            int idx = tid + i*512;
            int arr = idx >> 10, rem = idx & 1023;
            int row = rem >> 2, seg = rem & 3;
            uint32_t so = 2*OL_A_B + (uint32_t)arr*OL_B_B + (uint32_t)((row*SAS + seg*8)*2);
            size_t g = (size_t)row*DI + k0 + seg*8;
            cpa16(sbase + so, arr ? (const void*)&g_wolo[g] : (const void*)&g_wohi[g]);
        }
        CPA_COMMIT();
    };

    uint32_t aoff = (uint32_t)(((wm*32 + (lane&15))*SAS + (lane>>4)*8) * 2);
    uint32_t boff = 2*OL_A_B + (uint32_t)(((wn*64 + (lane&7))*SAS + ((lane>>3)&1)*8) * 2);

    issue(0, 0);
    issue(1, 1);

    #pragma unroll
    for (int k = 0; k < 8; k++) {
        if (k < 7) asm volatile("cp.async.wait_group 1;" ::: "memory");
        else       asm volatile("cp.async.wait_group 0;" ::: "memory");
        __syncthreads();
        int stg = k & 1;
        uint32_t aBase = sb + (uint32_t)stg*OL_STG + aoff;
        uint32_t bBase = sb + (uint32_t)stg*OL_STG + boff;
        #pragma unroll
        for (int ks = 0; ks < 2; ks++) {
            uint32_t koff = ks*32;
            uint32_t ah[2][4], al[2][4], bh[8][2], bl[8][2];
            #pragma unroll
            for (int mi = 0; mi < 2; mi++) {
                ldsm4(ah[mi], aBase + mi*(16*SAS*2) + koff);
                ldsm4(al[mi], aBase + OL_A_B + mi*(16*SAS*2) + koff);
            }
            #pragma unroll
            for (int ni = 0; ni < 8; ni++) {
                ldsm2(bh[ni], bBase + ni*(8*SAS*2) + koff);
                ldsm2(bl[ni], bBase + OL_B_B + ni*(8*SAS*2) + koff);
            }
            #pragma unroll
            for (int mi = 0; mi < 2; mi++)
                #pragma unroll
                for (int ni = 0; ni < 8; ni++) {
                    mma_bf16(acc[mi][ni], ah[mi], bh[ni]);
                    mma_bf16(acc[mi][ni], ah[mi], bl[ni]);
                    mma_bf16(acc[mi][ni], al[mi], bh[ni]);
                }
        }
        __syncthreads();
        if (k + 2 < 8) issue(k + 2, stg);
    }
    __syncthreads();

    float* stage = (float*)dsm;
    float* mu = (float*)(dsm + 256*36*4);
    float* rs = mu + 32;
    uint32_t xb_base = sb + 256*36*4 + 256;
    float* xb_ptr = (float*)(dsm + 256*36*4 + 256);

    auto issue_x = [&](int p) {
        uint32_t dst = xb_base + (uint32_t)(p & 1)*OL_XB;
        int nb = n0 + p*32;
        #pragma unroll
        for (int i = 0; i < 4; i++) {
            int idx = tid + i*512;
            int c = idx >> 3, seg = idx & 7;
            cpa16(dst + (uint32_t)(c*32 + seg*4)*4,
                  &x[((size_t)b*DIMC + c)*NPT + nb + seg*4]);
        }
        CPA_COMMIT();
    };

    issue_x(0);
    for (int p = 0; p < 4; p++) {
        if (p + 1 < 4) issue_x(p + 1);
        if (wm == p) {
            #pragma unroll
            for (int mi = 0; mi < 2; mi++) {
                int rl = mi*16 + (lane>>2);
                #pragma unroll
                for (int ni = 0; ni < 8; ni++) {
                    int c = wn*64 + ni*8 + (lane&3)*2;
                    float b0 = bout[c], b1 = bout[c+1];
                    stage[(size_t)c*36 + rl]         = acc[mi][ni][0] + b0;
                    stage[(size_t)(c+1)*36 + rl]     = acc[mi][ni][1] + b1;
                    stage[(size_t)c*36 + rl + 8]     = acc[mi][ni][2] + b0;
                    stage[(size_t)(c+1)*36 + rl + 8] = acc[mi][ni][3] + b1;
                }
            }
        }
        if (p + 1 < 4) asm volatile("cp.async.wait_group 1;" ::: "memory");
        else           asm volatile("cp.async.wait_group 0;" ::: "memory");
        __syncthreads();
        float* xb = xb_ptr + (p & 1)*(OL_XB/4);
        for (int idx = tid; idx < 8192; idx += 512) {
            int c = idx >> 5, nn = idx & 31;
            stage[(size_t)c*36 + nn] += xb[c*32 + nn];
        }
        __syncthreads();
        {
            int nn = wid*2 + (lane>>4);
            int h = lane & 15;
            float sum = 0.f, sq = 0.f;
            #pragma unroll
            for (int c = h; c < 256; c += 16) {
                float v = stage[(size_t)c*36 + nn];
                sum += v; sq += v*v;
            }
            #pragma unroll
            for (int o = 1; o < 16; o <<= 1) {
                sum += __shfl_xor_sync(0xFFFFFFFFu, sum, o);
                sq  += __shfl_xor_sync(0xFFFFFFFFu, sq,  o);
            }
            if (h == 0) {
                float m = sum * (1.f/256.f);
                mu[nn] = m;
                rs[nn] = rsqrtf(sq * (1.f/256.f) - m*m + 1e-5f);
            }
        }
        __syncthreads();
        int nb = n0 + p*32;
        for (int idx = tid; idx < 8192; idx += 512) {
            int c = idx >> 5, nn = idx & 31;
            float v = (stage[(size_t)c*36 + nn] - mu[nn]) * rs[nn] * gamma[c] + beta[c];
            out[((size_t)b*DIMC + c)*NPT + nb + nn] = v;
        }
        __syncthreads();
    }
}

// ---------------- launch ------------------------------------------------------
extern "C" void kernel_launch(void* const* d_in, const int* in_sizes, int n_in,
                              void* d_out, int out_size) {
    const float* x      = (const float*)d_in[0];
    const float* w_in   = (const float*)d_in[1];
    const float* b_in   = (const float*)d_in[2];
    const float* w_conv = (const float*)d_in[3];
    const float* b_conv = (const float*)d_in[4];
    const float* A_log  = (const float*)d_in[5];
    const float* D_skip = (const float*)d_in[6];
    const float* Bw     = (const float*)d_in[7];
    const float* Cw     = (const float*)d_in[8];
    const float* w_out  = (const float*)d_in[9];
    const float* b_out  = (const float*)d_in[10];
    const float* gamma  = (const float*)d_in[11];
    const float* beta   = (const float*)d_in[12];
    float* out = (float*)d_out;

    cudaFuncSetAttribute(k_mma_in,     cudaFuncAttributeMaxDynamicSharedMemorySize, MMA_DSM);
    cudaFuncSetAttribute(k_mma_out_ln, cudaFuncAttributeMaxDynamicSharedMemorySize, OL_DSM);

    k_prep<<<816 + 2048, 256>>>(A_log, w_in, w_out, Bw, Cw, x);
    k_mma_in<<<dim3(32, 4, BATCH), 256, MMA_DSM>>>(b_in);
    k_convz<<<dim3(64, 4, BATCH), 256>>>(w_conv, b_conv);
    k_mma_bc<<<256, 256>>>();
    k_scan1<<<dim3(NC, BATCH), 256>>>();
    k_scan2<<<64, 256>>>();
    k_scan3<<<dim3(NC, BATCH), 256>>>(D_skip);
    k_mma_out_ln<<<128, 512, OL_DSM>>>(x, b_out, gamma, beta, out);
}